// round 2
// baseline (speedup 1.0000x reference)
#include <cuda_runtime.h>

// Problem shape (fixed by setup_inputs): x (B=1024, S=1024, E=12), n_qubits = 12.
#define BB   1024
#define SSZ  1024
#define EE   12
#define EPSV 1e-5f
#define BPB  8      // b-values per thread in main kernel

// Scratch tables: attn[s][e], ffn[s][e]  (s in 0..1023, e in 0..11)
__device__ float g_attn[BB * EE];
__device__ float g_ffn [BB * EE];

// ---------------------------------------------------------------------------
// Kernel 1: per-row quantum "attention" and "ffn" tables.
//   z_i        = cos(rx[i]) * cos(x[j,i,0])
//   attn[j,0]  = prod_{i=1..11} z_i ;  attn[j,w] = prod_{i=0..w} z_i
//   tok2[j,i]  = LN1(x[j,i,:] + attn[i,:])[0]
//   r_i        = relu(cos(tok2[j,i] + ry[i]))
//   ffn[j,e]   = b_ffn[e] + sum_i r_i * w_ffn[e,i]
// One warp per j; 256 blocks x 128 threads (4 warps) = 1024 warps.
// ---------------------------------------------------------------------------
__global__ __launch_bounds__(128) void qtb_k1(
    const float* __restrict__ x,
    const float* __restrict__ rxa,
    const float* __restrict__ rya,
    const float* __restrict__ wffn,   // (E, 12) row-major
    const float* __restrict__ bffn,
    const float* __restrict__ g1,
    const float* __restrict__ b1)
{
    __shared__ float s_attn12[12][12];   // attn rows 0..11 (needed for tok2)

    const int tid = threadIdx.x;

    // Phase A0: attn rows 0..11 into smem. 144 items over 128 threads
    // (strided loop — previous version used `if (tid < 144)` with a
    // 128-thread block, leaving rows 10-11 uninitialized).
    for (int t = tid; t < 144; t += 128) {
        const int i = t / 12;
        const int w = t % 12;
        float z[12];
        #pragma unroll
        for (int k = 0; k < 12; k++)
            z[k] = cosf(__ldg(&rxa[k])) * cosf(__ldg(&x[(size_t)i * SSZ * EE + k * EE]));
        float p = 1.0f;
        if (w == 0) {
            #pragma unroll
            for (int k = 1; k < 12; k++) p *= z[k];
        } else {
            for (int k = 0; k <= w; k++) p *= z[k];
        }
        s_attn12[i][w] = p;
    }
    __syncthreads();

    const int warp = tid >> 5;
    const int lane = tid & 31;
    const int j    = blockIdx.x * 4 + warp;   // 0..1023
    const size_t rowbase = (size_t)j * SSZ * EE;

    // Phase A: this warp's own attn row (lane i holds z_i, shuffle products)
    float zl = 0.0f;
    if (lane < 12)
        zl = cosf(__ldg(&rxa[lane])) * cosf(x[rowbase + lane * EE]);
    float aw = 1.0f;
    #pragma unroll
    for (int k = 0; k < 12; k++) {
        float zk = __shfl_sync(0xffffffffu, zl, k);
        bool incl = (lane == 0) ? (k >= 1) : (k <= lane);
        if (incl) aw *= zk;
    }
    if (lane < 12) g_attn[j * 12 + lane] = aw;

    // Phase B: lane i<12 computes tok2_i via the 12-wide LN of row (j,i)
    float r = 0.0f;
    if (lane < 12) {
        float v[12];
        float mu = 0.0f;
        #pragma unroll
        for (int e = 0; e < 12; e++) {
            v[e] = x[rowbase + lane * EE + e] + s_attn12[lane][e];
            mu  += v[e];
        }
        mu *= (1.0f / 12.0f);
        float var = 0.0f;
        #pragma unroll
        for (int e = 0; e < 12; e++) { float d = v[e] - mu; var += d * d; }
        var *= (1.0f / 12.0f);
        const float inv  = rsqrtf(var + EPSV);
        const float tok2 = (v[0] - mu) * inv * __ldg(&g1[0]) + __ldg(&b1[0]);
        r = fmaxf(cosf(tok2 + __ldg(&rya[lane])), 0.0f);
    }

    // Phase C: ffn[j,e] = b_ffn[e] + sum_i r_i * w_ffn[e,i]
    float acc = (lane < 12) ? __ldg(&bffn[lane]) : 0.0f;
    #pragma unroll
    for (int i = 0; i < 12; i++) {
        float ri = __shfl_sync(0xffffffffu, r, i);
        if (lane < 12) acc = fmaf(ri, __ldg(&wffn[lane * 12 + i]), acc);
    }
    if (lane < 12) g_ffn[j * 12 + lane] = acc;
}

// ---------------------------------------------------------------------------
// Kernel 2: out[b,s,:] = LN2( LN1(x[b,s,:] + attn[s,:]) + ffn[s,:] )
// Thread owns one s, loops over BPB b-values (attn/ffn stay in registers).
// grid (SSZ/256, BB/BPB), 256 threads. Warp-contiguous 48B/thread accesses.
// ---------------------------------------------------------------------------
__global__ __launch_bounds__(256) void qtb_k2(
    const float* __restrict__ x,
    const float* __restrict__ g1, const float* __restrict__ b1,
    const float* __restrict__ g2, const float* __restrict__ b2,
    float* __restrict__ out)
{
    __shared__ float sG1[12], sB1[12], sG2[12], sB2[12];
    if (threadIdx.x < 12) {
        sG1[threadIdx.x] = g1[threadIdx.x];
        sB1[threadIdx.x] = b1[threadIdx.x];
        sG2[threadIdx.x] = g2[threadIdx.x];
        sB2[threadIdx.x] = b2[threadIdx.x];
    }
    __syncthreads();

    const int s  = blockIdx.x * blockDim.x + threadIdx.x;   // 0..1023
    const int b0 = blockIdx.y * BPB;

    // attn[s,:], ffn[s,:] in registers (tables are L2-resident, 96 KB total)
    float attn[12], ffn[12];
    {
        const float4* ap = reinterpret_cast<const float4*>(&g_attn[s * 12]);
        const float4* fp = reinterpret_cast<const float4*>(&g_ffn [s * 12]);
        float4 a0 = ap[0], a1 = ap[1], a2 = ap[2];
        float4 f0 = fp[0], f1 = fp[1], f2 = fp[2];
        attn[0]=a0.x; attn[1]=a0.y; attn[2]=a0.z; attn[3]=a0.w;
        attn[4]=a1.x; attn[5]=a1.y; attn[6]=a1.z; attn[7]=a1.w;
        attn[8]=a2.x; attn[9]=a2.y; attn[10]=a2.z; attn[11]=a2.w;
        ffn[0]=f0.x; ffn[1]=f0.y; ffn[2]=f0.z; ffn[3]=f0.w;
        ffn[4]=f1.x; ffn[5]=f1.y; ffn[6]=f1.z; ffn[7]=f1.w;
        ffn[8]=f2.x; ffn[9]=f2.y; ffn[10]=f2.z; ffn[11]=f2.w;
    }

    #pragma unroll 2
    for (int bi = 0; bi < BPB; bi++) {
        const size_t base = ((size_t)(b0 + bi) * SSZ + s) * EE;
        const float4* xp = reinterpret_cast<const float4*>(x + base);
        float4 q0 = xp[0], q1 = xp[1], q2 = xp[2];

        float v[12];
        v[0]=q0.x; v[1]=q0.y; v[2]=q0.z; v[3]=q0.w;
        v[4]=q1.x; v[5]=q1.y; v[6]=q1.z; v[7]=q1.w;
        v[8]=q2.x; v[9]=q2.y; v[10]=q2.z; v[11]=q2.w;

        // x + attn, LN1
        float mu = 0.0f;
        #pragma unroll
        for (int e = 0; e < 12; e++) { v[e] += attn[e]; mu += v[e]; }
        mu *= (1.0f / 12.0f);
        float var = 0.0f;
        #pragma unroll
        for (int e = 0; e < 12; e++) { float d = v[e] - mu; var += d * d; }
        var *= (1.0f / 12.0f);
        const float inv = rsqrtf(var + EPSV);

        // x1 + ffn, LN2
        float u[12];
        float mu2 = 0.0f;
        #pragma unroll
        for (int e = 0; e < 12; e++) {
            u[e] = (v[e] - mu) * inv * sG1[e] + sB1[e] + ffn[e];
            mu2 += u[e];
        }
        mu2 *= (1.0f / 12.0f);
        float var2 = 0.0f;
        #pragma unroll
        for (int e = 0; e < 12; e++) { float d = u[e] - mu2; var2 += d * d; }
        var2 *= (1.0f / 12.0f);
        const float inv2 = rsqrtf(var2 + EPSV);

        float4 o0, o1, o2;
        o0.x = (u[0]  - mu2) * inv2 * sG2[0]  + sB2[0];
        o0.y = (u[1]  - mu2) * inv2 * sG2[1]  + sB2[1];
        o0.z = (u[2]  - mu2) * inv2 * sG2[2]  + sB2[2];
        o0.w = (u[3]  - mu2) * inv2 * sG2[3]  + sB2[3];
        o1.x = (u[4]  - mu2) * inv2 * sG2[4]  + sB2[4];
        o1.y = (u[5]  - mu2) * inv2 * sG2[5]  + sB2[5];
        o1.z = (u[6]  - mu2) * inv2 * sG2[6]  + sB2[6];
        o1.w = (u[7]  - mu2) * inv2 * sG2[7]  + sB2[7];
        o2.x = (u[8]  - mu2) * inv2 * sG2[8]  + sB2[8];
        o2.y = (u[9]  - mu2) * inv2 * sG2[9]  + sB2[9];
        o2.z = (u[10] - mu2) * inv2 * sG2[10] + sB2[10];
        o2.w = (u[11] - mu2) * inv2 * sG2[11] + sB2[11];

        float4* op = reinterpret_cast<float4*>(out + base);
        op[0] = o0; op[1] = o1; op[2] = o2;
    }
}

// ---------------------------------------------------------------------------
extern "C" void kernel_launch(void* const* d_in, const int* in_sizes, int n_in,
                              void* d_out, int out_size)
{
    const float* x    = (const float*)d_in[0];   // (1024, 1024, 12)
    const float* rxa  = (const float*)d_in[1];   // (12,)
    const float* rya  = (const float*)d_in[2];   // (12,)
    const float* wffn = (const float*)d_in[3];   // (12, 12)
    const float* bffn = (const float*)d_in[4];   // (12,)
    const float* g1   = (const float*)d_in[5];
    const float* b1   = (const float*)d_in[6];
    const float* g2   = (const float*)d_in[7];
    const float* b2   = (const float*)d_in[8];
    float* out = (float*)d_out;

    qtb_k1<<<BB / 4, 128>>>(x, rxa, rya, wffn, bffn, g1, b1);
    qtb_k2<<<dim3(SSZ / 256, BB / BPB), 256>>>(x, g1, b1, g2, b2, out);
}

// round 4
// speedup vs baseline: 1.1872x; 1.1872x over previous
#include <cuda_runtime.h>

// Problem shape (fixed by setup_inputs): x (B=1024, S=1024, E=12), n_qubits = 12.
#define BB    1024
#define SSZ   1024
#define EE    12
#define EPSV  1e-5f
#define CHUNK 128    // s-rows per block in k2
#define BPB   8      // b-values per block in k2

// Scratch tables: attn[s][e], ffn[s][e]  (s in 0..1023, e in 0..11)
__device__ float g_attn[BB * EE];
__device__ float g_ffn [BB * EE];

// ---------------------------------------------------------------------------
// Kernel 1: per-row quantum "attention" and "ffn" tables.
//   z_i        = cos(rx[i]) * cos(x[j,i,0])
//   attn[j,0]  = prod_{i=1..11} z_i ;  attn[j,w] = prod_{i=0..w} z_i
//   tok2[j,i]  = LN1(x[j,i,:] + attn[i,:])[0]
//   r_i        = relu(cos(tok2[j,i] + ry[i]))
//   ffn[j,e]   = b_ffn[e] + sum_i r_i * w_ffn[e,i]
// One warp per j; 128 blocks x 256 threads (8 warps). x[j,0:12,0:12] is a
// contiguous 144-float run -> staged into smem with coalesced float4 loads.
// ---------------------------------------------------------------------------
__global__ __launch_bounds__(256) void qtb_k1(
    const float* __restrict__ x,
    const float* __restrict__ rxa,
    const float* __restrict__ rya,
    const float* __restrict__ wffn,   // (E, 12) row-major
    const float* __restrict__ bffn,
    const float* __restrict__ g1,
    const float* __restrict__ b1)
{
    __shared__ float s_attn12[12][12];            // attn rows 0..11 (for tok2)
    __shared__ __align__(16) float swx[8][148];   // per-warp x[j,0:12,0:12]
    __shared__ float scrx[12];

    const int tid  = threadIdx.x;
    const int warp = tid >> 5;
    const int lane = tid & 31;
    const int j    = blockIdx.x * 8 + warp;       // 0..1023

    if (tid < 12) scrx[tid] = cosf(__ldg(&rxa[tid]));

    // Stage this warp's 144 contiguous floats (36 float4, coalesced)
    {
        const float4* xr = reinterpret_cast<const float4*>(x + (size_t)j * SSZ * EE);
        float4* sw = reinterpret_cast<float4*>(&swx[warp][0]);
        for (int t = lane; t < 36; t += 32) sw[t] = xr[t];
    }

    // Phase A0: attn rows 0..11 into smem (one item per thread, 144 of 256)
    if (tid < 144) {
        const int i = tid / 12;
        const int w = tid % 12;
        float z[12];
        #pragma unroll
        for (int k = 0; k < 12; k++)
            z[k] = cosf(__ldg(&rxa[k])) * cosf(__ldg(&x[(size_t)i * SSZ * EE + k * EE]));
        float p = 1.0f;
        if (w == 0) {
            #pragma unroll
            for (int k = 1; k < 12; k++) p *= z[k];
        } else {
            for (int k = 0; k <= w; k++) p *= z[k];
        }
        s_attn12[i][w] = p;
    }
    __syncthreads();

    // Phase A: this warp's own attn row (lane i holds z_i, shuffle products)
    float zl = 0.0f;
    if (lane < 12)
        zl = scrx[lane] * cosf(swx[warp][lane * 12]);
    float aw = 1.0f;
    #pragma unroll
    for (int k = 0; k < 12; k++) {
        float zk = __shfl_sync(0xffffffffu, zl, k);
        bool incl = (lane == 0) ? (k >= 1) : (k <= lane);
        if (incl) aw *= zk;
    }
    if (lane < 12) g_attn[j * 12 + lane] = aw;

    // Phase B: lane i<12 computes tok2_i via the 12-wide LN of row (j,i)
    float r = 0.0f;
    if (lane < 12) {
        float v[12];
        float mu = 0.0f;
        #pragma unroll
        for (int e = 0; e < 12; e++) {
            v[e] = swx[warp][lane * 12 + e] + s_attn12[lane][e];
            mu  += v[e];
        }
        mu *= (1.0f / 12.0f);
        float var = 0.0f;
        #pragma unroll
        for (int e = 0; e < 12; e++) { float d = v[e] - mu; var += d * d; }
        var *= (1.0f / 12.0f);
        const float inv  = rsqrtf(var + EPSV);
        const float tok2 = (v[0] - mu) * inv * __ldg(&g1[0]) + __ldg(&b1[0]);
        r = fmaxf(cosf(tok2 + __ldg(&rya[lane])), 0.0f);
    }

    // Phase C: ffn[j,e] = b_ffn[e] + sum_i r_i * w_ffn[e,i]
    float acc = (lane < 12) ? __ldg(&bffn[lane]) : 0.0f;
    #pragma unroll
    for (int i = 0; i < 12; i++) {
        float ri = __shfl_sync(0xffffffffu, r, i);
        if (lane < 12) acc = fmaf(ri, __ldg(&wffn[lane * 12 + i]), acc);
    }
    if (lane < 12) g_ffn[j * 12 + lane] = acc;
}

// ---------------------------------------------------------------------------
// Kernel 2: out[b,s,:] = LN2( LN1(x[b,s,:] + attn[s,:]) + ffn[s,:] )
// Block owns a 128-s chunk; loops over BPB b-values. x staged into smem via
// fully-coalesced cp.async (double-buffered), outputs written back in place
// then stored coalesced. attn/ffn chunks staged once per block.
// grid (SSZ/CHUNK, BB/BPB), 128 threads.
// ---------------------------------------------------------------------------
__global__ __launch_bounds__(128) void qtb_k2(
    const float* __restrict__ x,
    const float* __restrict__ g1, const float* __restrict__ b1,
    const float* __restrict__ g2, const float* __restrict__ b2,
    float* __restrict__ out)
{
    __shared__ __align__(16) float s_attn[CHUNK * 12];   // 6 KB
    __shared__ __align__(16) float s_ffn [CHUNK * 12];   // 6 KB
    __shared__ __align__(16) float sx[2][CHUNK * 12];    // 12 KB
    __shared__ float sG1[12], sB1[12], sG2[12], sB2[12];

    const int tid   = threadIdx.x;
    const int sbase = blockIdx.x * CHUNK;
    const int b0    = blockIdx.y * BPB;

    const float* xbase = x   + ((size_t)b0 * SSZ + sbase) * EE;
    float*       obase = out + ((size_t)b0 * SSZ + sbase) * EE;
    const size_t bstride = (size_t)SSZ * EE;   // one b step

    if (tid < 12) {
        sG1[tid] = g1[tid]; sB1[tid] = b1[tid];
        sG2[tid] = g2[tid]; sB2[tid] = b2[tid];
    }

    // Stage attn/ffn chunks (384 float4 each, coalesced; L2-hot across blocks)
    {
        const float4* ap = reinterpret_cast<const float4*>(g_attn + sbase * 12);
        const float4* fp = reinterpret_cast<const float4*>(g_ffn  + sbase * 12);
        float4* sa = reinterpret_cast<float4*>(s_attn);
        float4* sf = reinterpret_cast<float4*>(s_ffn);
        #pragma unroll
        for (int k = 0; k < 3; k++) {
            sa[tid + 128 * k] = ap[tid + 128 * k];
            sf[tid + 128 * k] = fp[tid + 128 * k];
        }
    }

    // cp.async stage of one 6 KB x-chunk into buffer `buf`
    auto issue_load = [&](int buf, int bi) {
        const float* src = xbase + (size_t)bi * bstride;
        unsigned dst = (unsigned)__cvta_generic_to_shared(&sx[buf][0]);
        #pragma unroll
        for (int k = 0; k < 3; k++) {
            asm volatile("cp.async.cg.shared.global [%0], [%1], 16;\n"
                         :: "r"(dst + (tid + 128 * k) * 16),
                            "l"(src + (tid + 128 * k) * 4));
        }
        asm volatile("cp.async.commit_group;\n");
    };

    issue_load(0, 0);

    for (int bi = 0; bi < BPB; bi++) {
        const int cur = bi & 1;
        if (bi + 1 < BPB) {
            issue_load(1 - cur, bi + 1);
            asm volatile("cp.async.wait_group 1;\n");
        } else {
            asm volatile("cp.async.wait_group 0;\n");
        }
        __syncthreads();   // buffer `cur` ready for all threads (+ tables on bi==0)

        // Thread owns row tid of the chunk. LDS.128 at 48 B stride: conflict-free.
        float4* row = reinterpret_cast<float4*>(&sx[cur][tid * 12]);
        float4 q0 = row[0], q1 = row[1], q2 = row[2];
        const float4* at = reinterpret_cast<const float4*>(&s_attn[tid * 12]);
        const float4* ft = reinterpret_cast<const float4*>(&s_ffn [tid * 12]);
        float4 a0 = at[0], a1 = at[1], a2 = at[2];
        float4 f0 = ft[0], f1 = ft[1], f2 = ft[2];

        float v[12], an[12], fn[12];
        v[0]=q0.x; v[1]=q0.y; v[2]=q0.z; v[3]=q0.w;
        v[4]=q1.x; v[5]=q1.y; v[6]=q1.z; v[7]=q1.w;
        v[8]=q2.x; v[9]=q2.y; v[10]=q2.z; v[11]=q2.w;
        an[0]=a0.x; an[1]=a0.y; an[2]=a0.z; an[3]=a0.w;
        an[4]=a1.x; an[5]=a1.y; an[6]=a1.z; an[7]=a1.w;
        an[8]=a2.x; an[9]=a2.y; an[10]=a2.z; an[11]=a2.w;
        fn[0]=f0.x; fn[1]=f0.y; fn[2]=f0.z; fn[3]=f0.w;
        fn[4]=f1.x; fn[5]=f1.y; fn[6]=f1.z; fn[7]=f1.w;
        fn[8]=f2.x; fn[9]=f2.y; fn[10]=f2.z; fn[11]=f2.w;

        // x + attn, LN1
        float mu = 0.0f;
        #pragma unroll
        for (int e = 0; e < 12; e++) { v[e] += an[e]; mu += v[e]; }
        mu *= (1.0f / 12.0f);
        float var = 0.0f;
        #pragma unroll
        for (int e = 0; e < 12; e++) { float d = v[e] - mu; var += d * d; }
        var *= (1.0f / 12.0f);
        const float inv = rsqrtf(var + EPSV);

        // x1 + ffn, LN2
        float u[12];
        float mu2 = 0.0f;
        #pragma unroll
        for (int e = 0; e < 12; e++) {
            u[e] = (v[e] - mu) * inv * sG1[e] + sB1[e] + fn[e];
            mu2 += u[e];
        }
        mu2 *= (1.0f / 12.0f);
        float var2 = 0.0f;
        #pragma unroll
        for (int e = 0; e < 12; e++) { float d = u[e] - mu2; var2 += d * d; }
        var2 *= (1.0f / 12.0f);
        const float inv2 = rsqrtf(var2 + EPSV);

        float4 o0, o1, o2;
        o0.x = (u[0]  - mu2) * inv2 * sG2[0]  + sB2[0];
        o0.y = (u[1]  - mu2) * inv2 * sG2[1]  + sB2[1];
        o0.z = (u[2]  - mu2) * inv2 * sG2[2]  + sB2[2];
        o0.w = (u[3]  - mu2) * inv2 * sG2[3]  + sB2[3];
        o1.x = (u[4]  - mu2) * inv2 * sG2[4]  + sB2[4];
        o1.y = (u[5]  - mu2) * inv2 * sG2[5]  + sB2[5];
        o1.z = (u[6]  - mu2) * inv2 * sG2[6]  + sB2[6];
        o1.w = (u[7]  - mu2) * inv2 * sG2[7]  + sB2[7];
        o2.x = (u[8]  - mu2) * inv2 * sG2[8]  + sB2[8];
        o2.y = (u[9]  - mu2) * inv2 * sG2[9]  + sB2[9];
        o2.z = (u[10] - mu2) * inv2 * sG2[10] + sB2[10];
        o2.w = (u[11] - mu2) * inv2 * sG2[11] + sB2[11];

        // Write results back in place (same thread, same slots: no hazard)
        row[0] = o0; row[1] = o1; row[2] = o2;
        __syncthreads();   // all rows written before cross-row coalesced store

        float4* dsto = reinterpret_cast<float4*>(obase + (size_t)bi * bstride);
        const float4* sv = reinterpret_cast<const float4*>(&sx[cur][0]);
        #pragma unroll
        for (int k = 0; k < 3; k++) dsto[tid + 128 * k] = sv[tid + 128 * k];
        __syncthreads();   // stores done before this buffer is overwritten (bi+2)
    }
}

// ---------------------------------------------------------------------------
extern "C" void kernel_launch(void* const* d_in, const int* in_sizes, int n_in,
                              void* d_out, int out_size)
{
    const float* x    = (const float*)d_in[0];   // (1024, 1024, 12)
    const float* rxa  = (const float*)d_in[1];   // (12,)
    const float* rya  = (const float*)d_in[2];   // (12,)
    const float* wffn = (const float*)d_in[3];   // (12, 12)
    const float* bffn = (const float*)d_in[4];   // (12,)
    const float* g1   = (const float*)d_in[5];
    const float* b1   = (const float*)d_in[6];
    const float* g2   = (const float*)d_in[7];
    const float* b2   = (const float*)d_in[8];
    float* out = (float*)d_out;

    qtb_k1<<<BB / 8, 256>>>(x, rxa, rya, wffn, bffn, g1, b1);
    qtb_k2<<<dim3(SSZ / CHUNK, BB / BPB), 128>>>(x, g1, b1, g2, b2, out);
}

// round 5
// speedup vs baseline: 1.4187x; 1.1951x over previous
#include <cuda_runtime.h>

// Problem shape (fixed by setup_inputs): x (B=1024, S=1024, E=12), n_qubits = 12.
#define BB    1024
#define SSZ   1024
#define EE    12
#define EPSV  1e-5f
#define CHUNK 128    // s-rows per block in k2
#define BPB   8      // b-values per block in k2
#define NSTG  3      // cp.async pipeline depth

// Scratch tables: attn[s][e], ffn[s][e]  (s in 0..1023, e in 0..11)
__device__ float g_attn[BB * EE];
__device__ float g_ffn [BB * EE];

// ---------------------------------------------------------------------------
// Kernel 1: per-row quantum "attention" and "ffn" tables (analytic collapse).
// One warp per j; 128 blocks x 256 threads.
// ---------------------------------------------------------------------------
__global__ __launch_bounds__(256) void qtb_k1(
    const float* __restrict__ x,
    const float* __restrict__ rxa,
    const float* __restrict__ rya,
    const float* __restrict__ wffn,   // (E, 12) row-major
    const float* __restrict__ bffn,
    const float* __restrict__ g1,
    const float* __restrict__ b1)
{
    __shared__ float s_attn12[12][12];            // attn rows 0..11 (for tok2)
    __shared__ __align__(16) float swx[8][148];   // per-warp x[j,0:12,0:12]
    __shared__ float scrx[12];

    const int tid  = threadIdx.x;
    const int warp = tid >> 5;
    const int lane = tid & 31;
    const int j    = blockIdx.x * 8 + warp;       // 0..1023

    if (tid < 12) scrx[tid] = __cosf(__ldg(&rxa[tid]));

    // Stage this warp's 144 contiguous floats (36 float4, coalesced)
    {
        const float4* xr = reinterpret_cast<const float4*>(x + (size_t)j * SSZ * EE);
        float4* sw = reinterpret_cast<float4*>(&swx[warp][0]);
        for (int t = lane; t < 36; t += 32) sw[t] = xr[t];
    }

    // Phase A0: attn rows 0..11 into smem (144 of 256 threads)
    if (tid < 144) {
        const int i = tid / 12;
        const int w = tid % 12;
        float z[12];
        #pragma unroll
        for (int k = 0; k < 12; k++)
            z[k] = __cosf(__ldg(&rxa[k])) * __cosf(__ldg(&x[(size_t)i * SSZ * EE + k * EE]));
        float p = 1.0f;
        if (w == 0) {
            #pragma unroll
            for (int k = 1; k < 12; k++) p *= z[k];
        } else {
            for (int k = 0; k <= w; k++) p *= z[k];
        }
        s_attn12[i][w] = p;
    }
    __syncthreads();

    // Phase A: this warp's own attn row (lane i holds z_i, shuffle products)
    float zl = 0.0f;
    if (lane < 12)
        zl = scrx[lane] * __cosf(swx[warp][lane * 12]);
    float aw = 1.0f;
    #pragma unroll
    for (int k = 0; k < 12; k++) {
        float zk = __shfl_sync(0xffffffffu, zl, k);
        bool incl = (lane == 0) ? (k >= 1) : (k <= lane);
        if (incl) aw *= zk;
    }
    if (lane < 12) g_attn[j * 12 + lane] = aw;

    // Phase B: lane i<12 computes tok2_i via the 12-wide LN of row (j,i)
    float r = 0.0f;
    if (lane < 12) {
        float v[12];
        float mu = 0.0f;
        #pragma unroll
        for (int e = 0; e < 12; e++) {
            v[e] = swx[warp][lane * 12 + e] + s_attn12[lane][e];
            mu  += v[e];
        }
        mu *= (1.0f / 12.0f);
        float var = 0.0f;
        #pragma unroll
        for (int e = 0; e < 12; e++) { float d = v[e] - mu; var += d * d; }
        var *= (1.0f / 12.0f);
        const float inv  = rsqrtf(var + EPSV);
        const float tok2 = (v[0] - mu) * inv * __ldg(&g1[0]) + __ldg(&b1[0]);
        r = fmaxf(__cosf(tok2 + __ldg(&rya[lane])), 0.0f);
    }

    // Phase C: ffn[j,e] = b_ffn[e] + sum_i r_i * w_ffn[e,i]
    float acc = (lane < 12) ? __ldg(&bffn[lane]) : 0.0f;
    #pragma unroll
    for (int i = 0; i < 12; i++) {
        float ri = __shfl_sync(0xffffffffu, r, i);
        if (lane < 12) acc = fmaf(ri, __ldg(&wffn[lane * 12 + i]), acc);
    }
    if (lane < 12) g_ffn[j * 12 + lane] = acc;
}

// ---------------------------------------------------------------------------
// Kernel 2: out[b,s,:] = LN2( LN1(x[b,s,:] + attn[s,:]) + ffn[s,:] )
// 3-stage cp.async pipeline for x; attn/ffn register-resident; output via
// direct strided STG.128 (per-warp 1536B contiguous -> full-line DRAM writes).
// One __syncthreads per iteration. grid (SSZ/CHUNK, BB/BPB), 128 threads.
// ---------------------------------------------------------------------------
__global__ __launch_bounds__(128) void qtb_k2(
    const float* __restrict__ x,
    const float* __restrict__ g1, const float* __restrict__ b1,
    const float* __restrict__ g2, const float* __restrict__ b2,
    float* __restrict__ out)
{
    __shared__ __align__(16) float sx[NSTG][CHUNK * 12];   // 18 KB
    __shared__ float sG1[12], sB1[12], sG2[12], sB2[12];

    const int tid   = threadIdx.x;
    const int sbase = blockIdx.x * CHUNK;
    const int b0    = blockIdx.y * BPB;
    const int s     = sbase + tid;

    const float* xbase = x   + ((size_t)b0 * SSZ + sbase) * EE;
    float*       obase = out + ((size_t)b0 * SSZ + s) * EE;   // this thread's row
    const size_t bstride = (size_t)SSZ * EE;

    if (tid < 12) {
        sG1[tid] = g1[tid]; sB1[tid] = b1[tid];
        sG2[tid] = g2[tid]; sB2[tid] = b2[tid];
    }

    // attn/ffn for this thread's row -> registers (g_* tables are L2-hot)
    float an[12], fn[12];
    {
        const float4* ap = reinterpret_cast<const float4*>(&g_attn[s * 12]);
        const float4* fp = reinterpret_cast<const float4*>(&g_ffn [s * 12]);
        float4 a0 = ap[0], a1 = ap[1], a2 = ap[2];
        float4 f0 = fp[0], f1 = fp[1], f2 = fp[2];
        an[0]=a0.x; an[1]=a0.y; an[2]=a0.z; an[3]=a0.w;
        an[4]=a1.x; an[5]=a1.y; an[6]=a1.z; an[7]=a1.w;
        an[8]=a2.x; an[9]=a2.y; an[10]=a2.z; an[11]=a2.w;
        fn[0]=f0.x; fn[1]=f0.y; fn[2]=f0.z; fn[3]=f0.w;
        fn[4]=f1.x; fn[5]=f1.y; fn[6]=f1.z; fn[7]=f1.w;
        fn[8]=f2.x; fn[9]=f2.y; fn[10]=f2.z; fn[11]=f2.w;
    }

    // cp.async stage of one 6 KB x-chunk into pipeline stage `buf`
    auto issue_load = [&](int buf, int bi) {
        const float* src = xbase + (size_t)bi * bstride;
        unsigned dst = (unsigned)__cvta_generic_to_shared(&sx[buf][0]);
        #pragma unroll
        for (int k = 0; k < 3; k++) {
            asm volatile("cp.async.cg.shared.global [%0], [%1], 16;\n"
                         :: "r"(dst + (tid + 128 * k) * 16),
                            "l"(src + (tid + 128 * k) * 4));
        }
        asm volatile("cp.async.commit_group;\n");
    };

    issue_load(0, 0);
    issue_load(1, 1);

    for (int bi = 0; bi < BPB; bi++) {
        if (bi + 2 < BPB) asm volatile("cp.async.wait_group 1;\n");
        else              asm volatile("cp.async.wait_group 0;\n");
        __syncthreads();   // buffer bi%NSTG ready for all; all threads past iter bi-1
        if (bi + 2 < BPB) issue_load((bi + 2) % NSTG, bi + 2);
        // (overwrites buffer last read at iter bi-1 -> safe after the sync above)

        const int cur = bi % NSTG;
        // Thread owns row tid. LDS.128 at 48B stride: conflict-free.
        const float4* row = reinterpret_cast<const float4*>(&sx[cur][tid * 12]);
        float4 q0 = row[0], q1 = row[1], q2 = row[2];

        float v[12];
        v[0]=q0.x; v[1]=q0.y; v[2]=q0.z; v[3]=q0.w;
        v[4]=q1.x; v[5]=q1.y; v[6]=q1.z; v[7]=q1.w;
        v[8]=q2.x; v[9]=q2.y; v[10]=q2.z; v[11]=q2.w;

        // x + attn, LN1
        float mu = 0.0f;
        #pragma unroll
        for (int e = 0; e < 12; e++) { v[e] += an[e]; mu += v[e]; }
        mu *= (1.0f / 12.0f);
        float var = 0.0f;
        #pragma unroll
        for (int e = 0; e < 12; e++) { float d = v[e] - mu; var += d * d; }
        var *= (1.0f / 12.0f);
        const float inv = rsqrtf(var + EPSV);

        // x1 + ffn, LN2
        float u[12];
        float mu2 = 0.0f;
        #pragma unroll
        for (int e = 0; e < 12; e++) {
            u[e] = (v[e] - mu) * inv * sG1[e] + sB1[e] + fn[e];
            mu2 += u[e];
        }
        mu2 *= (1.0f / 12.0f);
        float var2 = 0.0f;
        #pragma unroll
        for (int e = 0; e < 12; e++) { float d = u[e] - mu2; var2 += d * d; }
        var2 *= (1.0f / 12.0f);
        const float inv2 = rsqrtf(var2 + EPSV);

        float4 o0, o1, o2;
        o0.x = (u[0]  - mu2) * inv2 * sG2[0]  + sB2[0];
        o0.y = (u[1]  - mu2) * inv2 * sG2[1]  + sB2[1];
        o0.z = (u[2]  - mu2) * inv2 * sG2[2]  + sB2[2];
        o0.w = (u[3]  - mu2) * inv2 * sG2[3]  + sB2[3];
        o1.x = (u[4]  - mu2) * inv2 * sG2[4]  + sB2[4];
        o1.y = (u[5]  - mu2) * inv2 * sG2[5]  + sB2[5];
        o1.z = (u[6]  - mu2) * inv2 * sG2[6]  + sB2[6];
        o1.w = (u[7]  - mu2) * inv2 * sG2[7]  + sB2[7];
        o2.x = (u[8]  - mu2) * inv2 * sG2[8]  + sB2[8];
        o2.y = (u[9]  - mu2) * inv2 * sG2[9]  + sB2[9];
        o2.z = (u[10] - mu2) * inv2 * sG2[10] + sB2[10];
        o2.w = (u[11] - mu2) * inv2 * sG2[11] + sB2[11];

        // Direct store: 48B/thread, warp covers 1536B contiguous (full lines)
        float4* op = reinterpret_cast<float4*>(obase + (size_t)bi * bstride);
        op[0] = o0; op[1] = o1; op[2] = o2;
    }
}

// ---------------------------------------------------------------------------
extern "C" void kernel_launch(void* const* d_in, const int* in_sizes, int n_in,
                              void* d_out, int out_size)
{
    const float* x    = (const float*)d_in[0];   // (1024, 1024, 12)
    const float* rxa  = (const float*)d_in[1];   // (12,)
    const float* rya  = (const float*)d_in[2];   // (12,)
    const float* wffn = (const float*)d_in[3];   // (12, 12)
    const float* bffn = (const float*)d_in[4];   // (12,)
    const float* g1   = (const float*)d_in[5];
    const float* b1   = (const float*)d_in[6];
    const float* g2   = (const float*)d_in[7];
    const float* b2   = (const float*)d_in[8];
    float* out = (float*)d_out;

    qtb_k1<<<BB / 8, 256>>>(x, rxa, rya, wffn, bffn, g1, b1);
    qtb_k2<<<dim3(SSZ / CHUNK, BB / BPB), 128>>>(x, g1, b1, g2, b2, out);
}